// round 7
// baseline (speedup 1.0000x reference)
#include <cuda_runtime.h>
#include <cstdint>

// Fixed shapes from reference
#define B_    256
#define T_    2048
#define C_    44                   // A*D floats per (b,t) row
#define C4_   11                   // float4 per row (176 B); f4 never crosses a row
#define F4B   (T_ * C4_)           // 22528 float4 per batch
#define TPB   256
#define BPB   (F4B / TPB)          // 88 blocks per batch
#define GRID  (B_ * BPB)           // 22528 blocks (round-1 streaming shape)

// Per-batch gap bounds, zero-sentinel encoded (zero-init at module load, reset
// by the filler block each launch -> replay-deterministic, no init pass):
//   g_enc_min[b] = max over NaN rows of (T - t)   -> first NaN = T - g_enc_min
//   g_max[b]     = max over NaN rows of t         -> last NaN
__device__ int g_enc_min[B_];
__device__ int g_max[B_];
__device__ int g_cnt[B_];

__device__ __forceinline__ bool is_nan_bits(float f) {
    unsigned u = __float_as_uint(f);
    return (u & 0x7fffffffu) > 0x7f800000u;
}

// Single kernel, one float4 per thread (the proven bandwidth-optimal shape).
// The bulk load doubles as the NaN witness (gap rows are NaN in all channels,
// so v.x classifies the float4). NaN float4s skip the store and feed per-block
// shared-atomic bounds -> per-batch global atomicMax. The 88th-arriving block
// of each batch fills that batch's gap, overlapped with other batches' streams.
__global__ void __launch_bounds__(TPB)
fused_stream_kernel(const float* __restrict__ x, float* __restrict__ out) {
    const int blk = blockIdx.x;
    const int b   = blk / BPB;                     // batch
    const int tid = threadIdx.x;
    const int idx = blk * TPB + tid;               // global float4 index

    __shared__ int sm_enc, sm_max, sm_rank;
    if (tid == 0) { sm_enc = 0; sm_max = 0; }
    __syncthreads();

    // ---- Phase A: stream one float4 (unconditional coalesced load) ----
    const float4 v = ((const float4*)x)[idx];
    const bool nan = is_nan_bits(v.x);
    if (!nan) {
        ((float4*)out)[idx] = v;                   // pass-through
    } else {
        const int t = (idx - b * F4B) / C4_;       // gap row (rare path)
        atomicMax(&sm_enc, T_ - t);
        atomicMax(&sm_max, t);
    }
    __syncthreads();

    // ---- Publish + arrive ----
    if (tid == 0) {
        if (sm_max) {                              // block touched the gap
            atomicMax(&g_enc_min[b], sm_enc);
            atomicMax(&g_max[b], sm_max);
        }
        __threadfence();                           // release partials + stores
        sm_rank = atomicAdd(&g_cnt[b], 1);
    }
    __syncthreads();
    if (sm_rank != BPB - 1) return;                // not the last arriver

    // ---- Phase B: filler block for this batch ----
    __shared__ int sh_s, sh_e;
    if (tid == 0) {
        __threadfence();                           // acquire: partials visible
        sh_s = (T_ - g_enc_min[b]) - 1;            // last valid before gap
        sh_e = g_max[b] + 1;                       // first valid after gap
        g_enc_min[b] = 0;                          // self-clean for next replay
        g_max[b]     = 0;
        g_cnt[b]     = 0;
    }
    __syncthreads();

    const int   s   = sh_s;
    const int   e   = sh_e;
    const float inv = 1.0f / (float)(e - s);

    const float4* base4  = (const float4*)(x + (size_t)b * T_ * C_);
    const float4* xs_row = base4 + (size_t)s * C4_;  // L2-hot (just streamed)
    const float4* xe_row = base4 + (size_t)e * C4_;
    float4* bout = (float4*)(out + (size_t)b * T_ * C_);

    const int ngap4 = (e - s - 1) * C4_;           // <= 5632
    const int gbase = (s + 1) * C4_;

    for (int i = tid; i < ngap4; i += TPB) {
        const int dt = i / C4_;
        const int c  = i - dt * C4_;
        const float w  = (float)(dt + 1) * inv;
        const float4 a  = xs_row[c];
        const float4 bb = xe_row[c];
        float4 r;
        r.x = fmaf(bb.x - a.x, w, a.x);
        r.y = fmaf(bb.y - a.y, w, a.y);
        r.z = fmaf(bb.z - a.z, w, a.z);
        r.w = fmaf(bb.w - a.w, w, a.w);
        bout[gbase + i] = r;                       // coalesced, contiguous
    }
}

extern "C" void kernel_launch(void* const* d_in, const int* in_sizes, int n_in,
                              void* d_out, int out_size) {
    const float* x = (const float*)d_in[0];
    float* out = (float*)d_out;
    fused_stream_kernel<<<GRID, TPB>>>(x, out);
}

// round 8
// speedup vs baseline: 1.7017x; 1.7017x over previous
#include <cuda_runtime.h>
#include <cstdint>

// Fixed shapes from reference
#define B_    256
#define T_    2048
#define C_    44                 // A*D floats per (b,t) row
#define C4_   11                 // float4 per row (176 B); f4 never crosses a row
#define F4B   (T_ * C4_)         // 22528 float4 per batch
#define SPLIT 8                  // blocks per batch
#define TPB   256
#define CHUNK (F4B / SPLIT)      // 2816 float4 per block (= 256 t-rows)
#define IT1   (CHUNK / TPB)      // 11 float4 per thread

// Per-batch gap bounds (zero-sentinel encoding) + arrival counter.
// Zero-initialized at module load; the filler block resets them each launch
// -> replay-deterministic, no init pass.
//   g_enc_min[b] = max over NaN rows of (T - t)  -> first NaN = T - g_enc_min
//   g_max[b]     = max over NaN rows of t        -> last NaN
__device__ int g_enc_min[B_];
__device__ int g_max[B_];
__device__ int g_cnt[B_];

__device__ __forceinline__ bool is_nan_bits(float f) {
    unsigned u = __float_as_uint(f);
    return (u & 0x7fffffffu) > 0x7f800000u;
}

// Single kernel, 8 blocks/batch (grid = 2048 x 256), 11 float4 per thread.
// ALL 11 loads are issued into registers first (front-batched MLP=11), then
// classified: non-NaN -> store, NaN -> per-block bounds reduction. The bulk
// load doubles as the NaN witness (gap rows are NaN in all channels). The
// last-arriving block of each batch interpolates the gap from the L2-resident
// boundary rows, overlapped with other batches' streaming.
__global__ void __launch_bounds__(TPB)
fused_copy_fill_kernel(const float* __restrict__ x, float* __restrict__ out) {
    const int blk = blockIdx.x;
    const int b   = blk / SPLIT;
    const int q   = blk - b * SPLIT;
    const int tid = threadIdx.x;
    const int lbase = q * CHUNK + tid;             // local f4 index in batch
    const int idx0  = b * F4B + lbase;             // global f4 index

    const float4* __restrict__ xin  = (const float4*)x;
    float4*       __restrict__ xout = (float4*)out;

    __shared__ int sm_enc, sm_max, sm_rank;
    if (tid == 0) { sm_enc = 0; sm_max = 0; }

    // ---- Phase A1: front-batch ALL loads (MLP = 11) ----
    float4 v[IT1];
    #pragma unroll
    for (int k = 0; k < IT1; k++)
        v[k] = xin[idx0 + k * TPB];

    __syncthreads();                               // covers the sm_* init

    // ---- Phase A2: classify + store ----
    int tmin = T_, tmax = -1;
    #pragma unroll
    for (int k = 0; k < IT1; k++) {
        if (!is_nan_bits(v[k].x)) {
            xout[idx0 + k * TPB] = v[k];           // pass-through
        } else {
            const int t = (lbase + k * TPB) / C4_; // gap row (rare path)
            tmin = min(tmin, t);
            tmax = max(tmax, t);
        }
    }
    if (tmax >= 0) {
        atomicMax(&sm_enc, T_ - tmin);
        atomicMax(&sm_max, tmax);
    }
    __syncthreads();

    // ---- Publish + arrive (once per block, amortized over 2816 f4) ----
    if (tid == 0) {
        if (sm_max) {
            atomicMax(&g_enc_min[b], sm_enc);
            atomicMax(&g_max[b], sm_max);
        }
        __threadfence();                           // release partials
        sm_rank = atomicAdd(&g_cnt[b], 1);
    }
    __syncthreads();
    if (sm_rank != SPLIT - 1) return;              // not the last arriver

    // ---- Phase B: filler block for this batch ----
    __shared__ int sh_s, sh_e;
    if (tid == 0) {
        __threadfence();                           // acquire: partials visible
        sh_s = (T_ - g_enc_min[b]) - 1;            // last valid before gap
        sh_e = g_max[b] + 1;                       // first valid after gap
        g_enc_min[b] = 0;                          // self-clean for replay
        g_max[b]     = 0;
        g_cnt[b]     = 0;
    }
    __syncthreads();

    const int   s   = sh_s;
    const int   e   = sh_e;
    const float inv = 1.0f / (float)(e - s);

    const float4* base4  = (const float4*)(x + (size_t)b * T_ * C_);
    const float4* xs_row = base4 + (size_t)s * C4_;  // L2-hot (just streamed)
    const float4* xe_row = base4 + (size_t)e * C4_;
    float4* bout = (float4*)(out + (size_t)b * T_ * C_);

    const int ngap4 = (e - s - 1) * C4_;           // <= 5632
    const int gbase = (s + 1) * C4_;

    for (int i = tid; i < ngap4; i += TPB) {
        const int dt = i / C4_;
        const int c  = i - dt * C4_;
        const float w  = (float)(dt + 1) * inv;
        const float4 a  = xs_row[c];
        const float4 bb = xe_row[c];
        float4 r;
        r.x = fmaf(bb.x - a.x, w, a.x);
        r.y = fmaf(bb.y - a.y, w, a.y);
        r.z = fmaf(bb.z - a.z, w, a.z);
        r.w = fmaf(bb.w - a.w, w, a.w);
        bout[gbase + i] = r;                       // coalesced, contiguous
    }
}

extern "C" void kernel_launch(void* const* d_in, const int* in_sizes, int n_in,
                              void* d_out, int out_size) {
    const float* x = (const float*)d_in[0];
    float* out = (float*)d_out;
    fused_copy_fill_kernel<<<B_ * SPLIT, TPB>>>(x, out);
}

// round 9
// speedup vs baseline: 2.1769x; 1.2793x over previous
#include <cuda_runtime.h>
#include <cstdint>

// Fixed shapes from reference
#define B_    256
#define T_    2048
#define C_    44                 // A*D floats per (b,t) row
#define C4_   11                 // float4 per row (176 B); f4 never crosses a row
#define F4B   (T_ * C4_)         // 22528 float4 per batch
#define SPLIT 8                  // blocks per batch in kernel 1
#define TPB1  256
#define CHUNK (F4B / SPLIT)      // 2816 float4 per block (= 256 t-rows)
#define IT1   (CHUNK / TPB1)     // 11 float4 per thread

#define FILL_SPLIT 4             // fill blocks per batch
#define TPB2  128

// Per-block partial gap bounds {min_t, max_t}; every block rewrites its slot
// on every launch (replay-deterministic, no init pass, no global atomics).
__device__ int2 g_part[B_ * SPLIT];

__device__ __forceinline__ bool is_nan_bits(float f) {
    unsigned u = __float_as_uint(f);
    return (u & 0x7fffffffu) > 0x7f800000u;
}

// Kernel 1 (unchanged from round 5 -- measured at the streaming floor):
// stream-copy the whole tensor; the bulk load doubles as the NaN witness
// (gap rows are NaN in all channels, so v.x classifies the float4). NaN
// float4s skip the store (kernel 2 rewrites the gap) and feed a per-block
// min/max-t reduction.
__global__ void __launch_bounds__(TPB1)
copy_detect_kernel(const float* __restrict__ x, float* __restrict__ out) {
    const int blk = blockIdx.x;
    const int b   = blk / SPLIT;
    const int q   = blk - b * SPLIT;
    const int tid = threadIdx.x;
    const int idx0 = b * F4B + q * CHUNK;

    const float4* __restrict__ xin  = (const float4*)x;
    float4*       __restrict__ xout = (float4*)out;

    __shared__ int s_min, s_max;
    if (tid == 0) { s_min = T_; s_max = -1; }
    __syncthreads();

    int tmin = T_, tmax = -1;

    #pragma unroll
    for (int k = 0; k < IT1; k++) {
        const int idx = idx0 + tid + k * TPB1;
        const float4 v = xin[idx];                 // unconditional, coalesced
        if (!is_nan_bits(v.x)) {
            xout[idx] = v;                         // pass-through
        } else {
            const int t = (idx - b * F4B) / C4_;   // gap row (rare path)
            tmin = min(tmin, t);
            tmax = max(tmax, t);
        }
    }

    if (tmax >= 0) {                               // only gap-touching threads
        atomicMin(&s_min, tmin);
        atomicMax(&s_max, tmax);
    }
    __syncthreads();
    if (tid == 0) g_part[blk] = make_int2(s_min, s_max);
}

// Kernel 2: 4 blocks per batch, 128 threads, ZERO barriers.
// Every warp redundantly reduces the batch's 8 partials via shuffle
// (partials + boundary rows are L2-hot from kernel 1), then the block writes
// its interleaved quarter of the gap region with coalesced float4 stores.
__global__ void __launch_bounds__(TPB2)
gap_fill_kernel(const float* __restrict__ x, float* __restrict__ out) {
    const int blk = blockIdx.x;
    const int b   = blk / FILL_SPLIT;
    const int q   = blk - b * FILL_SPLIT;
    const int tid  = threadIdx.x;
    const int lane = tid & 31;

    // Warp-redundant partial reduction: lanes 0-7 each load one partial.
    int mn = T_, mx = -1;
    if (lane < SPLIT) {
        const int2 p = g_part[b * SPLIT + lane];   // L2-hot
        mn = p.x;
        mx = p.y;
    }
    #pragma unroll
    for (int o = 4; o > 0; o >>= 1) {
        mn = min(mn, __shfl_xor_sync(0xffffffffu, mn, o));
        mx = max(mx, __shfl_xor_sync(0xffffffffu, mx, o));
    }
    mn = __shfl_sync(0xffffffffu, mn, 0);
    mx = __shfl_sync(0xffffffffu, mx, 0);

    const int   s   = mn - 1;                      // last valid before gap
    const int   e   = mx + 1;                      // first valid after gap
    const float inv = 1.0f / (float)(e - s);

    const float4* base4  = (const float4*)(x + (size_t)b * T_ * C_);
    const float4* xs_row = base4 + (size_t)s * C4_;   // L2-hot
    const float4* xe_row = base4 + (size_t)e * C4_;
    float4* bout = (float4*)(out + (size_t)b * T_ * C_);

    const int ngap4 = (e - s - 1) * C4_;           // <= 5632
    const int gbase = (s + 1) * C4_;

    // Blocks of a batch interleave at 128-f4 granularity (coalesced stores).
    for (int i = q * TPB2 + tid; i < ngap4; i += FILL_SPLIT * TPB2) {
        const int dt = i / C4_;
        const int c  = i - dt * C4_;
        const float w  = (float)(dt + 1) * inv;
        const float4 a  = xs_row[c];
        const float4 bb = xe_row[c];
        float4 r;
        r.x = fmaf(bb.x - a.x, w, a.x);
        r.y = fmaf(bb.y - a.y, w, a.y);
        r.z = fmaf(bb.z - a.z, w, a.z);
        r.w = fmaf(bb.w - a.w, w, a.w);
        bout[gbase + i] = r;                       // coalesced, contiguous
    }
}

extern "C" void kernel_launch(void* const* d_in, const int* in_sizes, int n_in,
                              void* d_out, int out_size) {
    const float* x = (const float*)d_in[0];
    float* out = (float*)d_out;

    copy_detect_kernel<<<B_ * SPLIT, TPB1>>>(x, out);
    gap_fill_kernel<<<B_ * FILL_SPLIT, TPB2>>>(x, out);
}